// round 16
// baseline (speedup 1.0000x reference)
#include <cuda_runtime.h>
#include <cuda_bf16.h>
#include <cuda_fp16.h>

#define N_NODES 100000
#define N_EDGES 3200000
#define IN_DIM 128
#define HID 64
#define N_GRAPHS 64
#define BN_EPS 1e-5f

#define SCAN_NBLK 98        // ceil(100000 / 1024)
#define CNT_SCALE 1048576.0 // 2^20: counts in high bits, weight-sum in low
#define AGG_BLOCKS 12500    // N_NODES / 8
#define POOL_BLOCKS 782     // ceil(100000 / 128); 781*128 < N_NODES

// ---------------- scratch ----------------
__device__ __align__(16) double g_degcnt[N_NODES];     // w-sum + count*2^20
__device__ __align__(16) float g_dinv[N_NODES];
__device__ __align__(16) int   g_count[N_NODES];
__device__ __align__(16) int   g_off[N_NODES + 1];
__device__ __align__(16) int   g_cursor[N_NODES];
__device__ __align__(16) int   g_blocksum[SCAN_NBLK];
__device__ __align__(16) float2 g_csr[N_EDGES];        // {src_as_float, norm}
__device__ __align__(16) __half g_h[N_NODES * HID];    // gemm1 out (fp16)
__device__ __align__(16) __half g_h2[N_NODES * HID];   // gemm2 out (fp16)
__device__ __align__(16) float g_agg[N_NODES * HID];   // aggregation out (fp32)
__device__ double g_stats[4 * HID];
__device__ float g_A1[HID], g_B1[HID], g_A2[HID], g_B2[HID];
__device__ float g_pool[N_GRAPHS * HID];
__device__ float g_cnt[N_GRAPHS];
__device__ int   g_done[4];   // ticket counters: [0]=agg1, [1]=agg2, [2]=pool

// ---------------- init ----------------
__global__ void init_kernel() {
    int t = blockIdx.x * blockDim.x + threadIdx.x;
    if (t < N_NODES) g_degcnt[t] = 1.0;  // self-loop weight, count=0
    if (t < 4 * HID) g_stats[t] = 0.0;
    if (t < N_GRAPHS * HID) g_pool[t] = 0.0f;
    if (t < N_GRAPHS) g_cnt[t] = 0.0f;
    if (t < 4) g_done[t] = 0;
    if (t == 0) g_off[N_NODES] = N_EDGES;
}

// ---------------- fused weighted-degree + edge count (one atomic/edge) ----
__global__ void deg_count_kernel(const int* __restrict__ col,
                                 const float* __restrict__ w) {
    int e = blockIdx.x * blockDim.x + threadIdx.x;
    if (e < N_EDGES)
        atomicAdd(&g_degcnt[col[e]], (double)w[e] + CNT_SCALE);
}

// ---------------- scan phase A: unpack degcnt -> dinv/count; block sums ---
__global__ void scan_phaseA() {
    int blk = blockIdx.x;
    int tid = threadIdx.x;  // 256 threads
    int base = blk * 1024 + tid * 4;
    int s = 0;
#pragma unroll
    for (int i = 0; i < 4; i++) {
        int idx = base + i;
        if (idx < N_NODES) {
            double v = g_degcnt[idx];
            int cnt = (int)(v * (1.0 / CNT_SCALE));
            float wsum = (float)(v - (double)cnt * CNT_SCALE);
            g_count[idx] = cnt;
            g_dinv[idx] = rsqrtf(wsum);
            s += cnt;
        }
    }
    __shared__ int sh[256];
    sh[tid] = s;
    __syncthreads();
    for (int off = 128; off > 0; off >>= 1) {
        if (tid < off) sh[tid] += sh[tid + off];
        __syncthreads();
    }
    if (tid == 0) g_blocksum[blk] = sh[0];
}

// ---------------- scan phase C: self-computed block offset + local scan ---
__global__ void scan_phaseC() {
    int blk = blockIdx.x;
    int tid = threadIdx.x;  // 256 threads
    __shared__ int sh[256];
    // block offset = sum of blocksum[0 .. blk-1]  (blk <= 97 < 256)
    int v = (tid < blk) ? g_blocksum[tid] : 0;
    sh[tid] = v;
    __syncthreads();
    for (int off = 128; off > 0; off >>= 1) {
        if (tid < off) sh[tid] += sh[tid + off];
        __syncthreads();
    }
    int blockoff = sh[0];
    __syncthreads();
    // local exclusive scan over this block's 1024 counts
    int base = blk * 1024 + tid * 4;
    int c0 = 0, c1 = 0, c2 = 0, c3 = 0;
    if (base + 0 < N_NODES) c0 = g_count[base + 0];
    if (base + 1 < N_NODES) c1 = g_count[base + 1];
    if (base + 2 < N_NODES) c2 = g_count[base + 2];
    if (base + 3 < N_NODES) c3 = g_count[base + 3];
    int s = c0 + c1 + c2 + c3;
    sh[tid] = s;
    __syncthreads();
    for (int off = 1; off < 256; off <<= 1) {
        int u = (tid >= off) ? sh[tid - off] : 0;
        __syncthreads();
        sh[tid] += u;
        __syncthreads();
    }
    int run = blockoff + sh[tid] - s;
    if (base + 0 < N_NODES) { g_off[base + 0] = run; g_cursor[base + 0] = run; run += c0; }
    if (base + 1 < N_NODES) { g_off[base + 1] = run; g_cursor[base + 1] = run; run += c1; }
    if (base + 2 < N_NODES) { g_off[base + 2] = run; g_cursor[base + 2] = run; run += c2; }
    if (base + 3 < N_NODES) { g_off[base + 3] = run; g_cursor[base + 3] = run; run += c3; }
}

// ---------------- CSR fill (cursor atomics; packed 8B store) --------------
__global__ void fill_kernel(const int* __restrict__ row,
                            const int* __restrict__ col,
                            const float* __restrict__ w) {
    int e = blockIdx.x * blockDim.x + threadIdx.x;
    if (e >= N_EDGES) return;
    int r = row[e];
    int c = col[e];
    int pos = atomicAdd(&g_cursor[c], 1);
    g_csr[pos] = make_float2(__int_as_float(r), g_dinv[r] * w[e] * g_dinv[c]);
}

// ---------------- register-blocked GEMM: h16[n,64] = X[n,K] @ W[K,64] ----
// 256 threads, tile 32x64, 8 outputs/thread (4 rows x 2 cols), fp16 output.
// Warp-uniform rg -> sX reads are broadcast (no bank conflicts).
// WHICH==0: X = Xin, out = g_h.  WHICH==1: X = relu(A1*g_agg+B1), out = g_h2.
template <int K, int WHICH>
__global__ void gemm_kernel(const float* __restrict__ Xin,
                            const float* __restrict__ W) {
    __shared__ float sX[32][K];
    __shared__ float sW[K * 64];
    const float* X = WHICH ? (const float*)g_agg : Xin;
    __half2* out = reinterpret_cast<__half2*>(WHICH ? g_h2 : g_h);
    int tid = threadIdx.x;
    int node0 = blockIdx.x * 32;
    for (int i = tid; i < K * 64; i += 256) sW[i] = W[i];
    for (int i = tid; i < 32 * K; i += 256) {
        int r = i / K, c = i % K;
        float v = X[(size_t)(node0 + r) * K + c];
        if (WHICH) v = fmaxf(fmaf(g_A1[c], v, g_B1[c]), 0.0f);
        sX[r][c] = v;
    }
    __syncthreads();
    int c2 = (tid & 31) * 2;   // column pair
    int rg = tid >> 5;         // warp-uniform -> rows rg, rg+8, rg+16, rg+24
    float a0x = 0, a0y = 0, a1x = 0, a1y = 0, a2x = 0, a2y = 0, a3x = 0, a3y = 0;
#pragma unroll
    for (int k = 0; k < K; k++) {
        float2 wv = *(const float2*)&sW[k * 64 + c2];
        float x0 = sX[rg][k];
        float x1 = sX[rg + 8][k];
        float x2 = sX[rg + 16][k];
        float x3 = sX[rg + 24][k];
        a0x = fmaf(x0, wv.x, a0x); a0y = fmaf(x0, wv.y, a0y);
        a1x = fmaf(x1, wv.x, a1x); a1y = fmaf(x1, wv.y, a1y);
        a2x = fmaf(x2, wv.x, a2x); a2y = fmaf(x2, wv.y, a2y);
        a3x = fmaf(x3, wv.x, a3x); a3y = fmaf(x3, wv.y, a3y);
    }
    int jp = c2 >> 1;
    out[(size_t)(node0 + rg) * 32 + jp]      = __floats2half2_rn(a0x, a0y);
    out[(size_t)(node0 + rg + 8) * 32 + jp]  = __floats2half2_rn(a1x, a1y);
    out[(size_t)(node0 + rg + 16) * 32 + jp] = __floats2half2_rn(a2x, a2y);
    out[(size_t)(node0 + rg + 24) * 32 + jp] = __floats2half2_rn(a3x, a3y);
}

// ---------------- CSR gather-aggregate + fused BN stats + finalize --------
// agg[n,:] = dinv[n]^2*h[n,:] + b + sum_k norm[k]*h[src[k],:]
// 256 threads = 8 warps = 8 nodes/block; lane handles a channel pair (half2).
// Block reduces its 8 nodes' values -> double atomics into g_stats; the
// last-finishing block (ticket counter) computes the BN affine A/B.
__global__ void aggregate_kernel(const float* __restrict__ b,
                                 const float* __restrict__ gamma,
                                 const float* __restrict__ beta,
                                 int which) {
    const __half2* h = reinterpret_cast<const __half2*>(which ? g_h2 : g_h);
    int wid = threadIdx.x >> 5;
    int lane = threadIdx.x & 31;
    int node = blockIdx.x * 8 + wid;
    int j2 = lane;
    float2 bj = ((const float2*)b)[j2];
    float d = g_dinv[node];
    float d2 = d * d;
    float2 hf = __half22float2(h[(size_t)node * 32 + j2]);
    float2 acc;
    acc.x = fmaf(d2, hf.x, bj.x);
    acc.y = fmaf(d2, hf.y, bj.y);
    int s = g_off[node];
    int e = g_off[node + 1];
    int k = s;
    for (; k + 3 < e; k += 4) {
        float2 p0 = g_csr[k];
        float2 p1 = g_csr[k + 1];
        float2 p2 = g_csr[k + 2];
        float2 p3 = g_csr[k + 3];
        __half2 v0 = h[(size_t)__float_as_int(p0.x) * 32 + j2];
        __half2 v1 = h[(size_t)__float_as_int(p1.x) * 32 + j2];
        __half2 v2 = h[(size_t)__float_as_int(p2.x) * 32 + j2];
        __half2 v3 = h[(size_t)__float_as_int(p3.x) * 32 + j2];
        float2 f0 = __half22float2(v0);
        float2 f1 = __half22float2(v1);
        float2 f2 = __half22float2(v2);
        float2 f3 = __half22float2(v3);
        acc.x = fmaf(p0.y, f0.x, acc.x); acc.y = fmaf(p0.y, f0.y, acc.y);
        acc.x = fmaf(p1.y, f1.x, acc.x); acc.y = fmaf(p1.y, f1.y, acc.y);
        acc.x = fmaf(p2.y, f2.x, acc.x); acc.y = fmaf(p2.y, f2.y, acc.y);
        acc.x = fmaf(p3.y, f3.x, acc.x); acc.y = fmaf(p3.y, f3.y, acc.y);
    }
    for (; k < e; k++) {
        float2 p = g_csr[k];
        float2 f = __half22float2(h[(size_t)__float_as_int(p.x) * 32 + j2]);
        acc.x = fmaf(p.y, f.x, acc.x);
        acc.y = fmaf(p.y, f.y, acc.y);
    }
    ((float2*)g_agg)[(size_t)node * 32 + j2] = acc;

    // ---- fused BN stats: block reduction over 8 nodes ----
    __shared__ float4 red[8][32];
    red[wid][lane] = make_float4(acc.x, acc.y, acc.x * acc.x, acc.y * acc.y);
    __syncthreads();
    int off = which ? 128 : 0;
    if (wid == 0) {
        float4 t = red[0][lane];
#pragma unroll
        for (int w = 1; w < 8; w++) {
            float4 u = red[w][lane];
            t.x += u.x; t.y += u.y; t.z += u.z; t.w += u.w;
        }
        atomicAdd(&g_stats[off + 2 * lane],          (double)t.x);
        atomicAdd(&g_stats[off + 2 * lane + 1],      (double)t.y);
        atomicAdd(&g_stats[off + 64 + 2 * lane],     (double)t.z);
        atomicAdd(&g_stats[off + 64 + 2 * lane + 1], (double)t.w);
    }
    // ---- last-block finalize ----
    __threadfence();
    __syncthreads();
    __shared__ int sticket;
    if (threadIdx.x == 0) sticket = atomicAdd(&g_done[which], 1);
    __syncthreads();
    if (sticket == AGG_BLOCKS - 1 && threadIdx.x < 64) {
        int j = threadIdx.x;
        double sum = atomicAdd(&g_stats[off + j], 0.0);
        double ssq = atomicAdd(&g_stats[off + 64 + j], 0.0);
        double mean = sum / (double)N_NODES;
        double var = ssq / (double)N_NODES - mean * mean;
        float istd = rsqrtf((float)var + BN_EPS);
        float a = gamma[j] * istd;
        float bb = beta[j] - a * (float)mean;
        if (which == 0) { g_A1[j] = a; g_B1[j] = bb; }
        else            { g_A2[j] = a; g_B2[j] = bb; }
    }
}

// ---------------- fused BN2+ReLU + pool + output head (batch sorted) ------
__global__ void pool_kernel(const int* __restrict__ batch,
                            const float* __restrict__ Wout,
                            const float* __restrict__ bout,
                            float* __restrict__ out) {
    int j = threadIdx.x;  // 64 threads
    int r0 = blockIdx.x * 128;
    int rend = min(r0 + 128, N_NODES);
    float A = g_A2[j], B = g_B2[j];
    int cur = batch[r0];
    float s = 0.0f;
    int c = 0;
    for (int r = r0; r < rend; r++) {
        int gg = batch[r];
        if (gg != cur) {
            atomicAdd(&g_pool[cur * 64 + j], s);
            if (j == 0) atomicAdd(&g_cnt[cur], (float)c);
            s = 0.0f; c = 0; cur = gg;
        }
        float v = fmaxf(fmaf(A, g_agg[(size_t)r * 64 + j], B), 0.0f);
        s += v;
        c++;
    }
    atomicAdd(&g_pool[cur * 64 + j], s);
    if (j == 0) atomicAdd(&g_cnt[cur], (float)c);

    // ---- last-block output head ----
    __threadfence();
    __syncthreads();
    __shared__ int sticket;
    if (threadIdx.x == 0) sticket = atomicAdd(&g_done[2], 1);
    __syncthreads();
    if (sticket == POOL_BLOCKS - 1) {
        int g = threadIdx.x;  // 64 graphs, 64 threads
        float cg = fmaxf(atomicAdd(&g_cnt[g], 0.0f), 1.0f);
        float acc = 0.0f;
#pragma unroll
        for (int jj = 0; jj < HID; jj++)
            acc = fmaf(atomicAdd(&g_pool[g * HID + jj], 0.0f), Wout[jj], acc);
        out[g] = acc / cg + bout[0];
    }
}

// ---------------- launch ----------------
extern "C" void kernel_launch(void* const* d_in, const int* in_sizes, int n_in,
                              void* d_out, int out_size) {
    const float* x = (const float*)d_in[0];
    const int* ei = (const int*)d_in[1];
    const float* ew = (const float*)d_in[2];
    const int* batch = (const int*)d_in[3];
    const float* W1 = (const float*)d_in[4];
    const float* b1 = (const float*)d_in[5];
    const float* W2 = (const float*)d_in[6];
    const float* b2 = (const float*)d_in[7];
    const float* g1 = (const float*)d_in[8];
    const float* be1 = (const float*)d_in[9];
    const float* g2 = (const float*)d_in[10];
    const float* be2 = (const float*)d_in[11];
    const float* Wout = (const float*)d_in[12];
    const float* bout = (const float*)d_in[13];
    float* out = (float*)d_out;

    const int* row = ei;
    const int* col = ei + N_EDGES;

    const int EB = (N_EDGES + 255) / 256;
    const int NB = (N_NODES + 255) / 256;
    const int GB = N_NODES / 32;   // 3125, exact

    // ---- CSR build (once, reused by both layers) ----
    init_kernel<<<NB, 256>>>();
    deg_count_kernel<<<EB, 256>>>(col, ew);
    scan_phaseA<<<SCAN_NBLK, 256>>>();   // unpack degcnt + rsqrt + block sums
    scan_phaseC<<<SCAN_NBLK, 256>>>();   // self-computed offsets
    fill_kernel<<<EB, 256>>>(row, col, ew);

    // ---- layer 1 (aggregate also does BN1 stats + finalize) ----
    gemm_kernel<IN_DIM, 0><<<GB, 256>>>(x, W1);
    aggregate_kernel<<<AGG_BLOCKS, 256>>>(b1, g1, be1, 0);

    // ---- layer 2 (BN1+ReLU fused into GEMM X-load; BN2 stats in agg) ----
    gemm_kernel<HID, 1><<<GB, 256>>>(x /*unused*/, W2);
    aggregate_kernel<<<AGG_BLOCKS, 256>>>(b2, g2, be2, 1);

    // ---- pool + head (fused) ----
    pool_kernel<<<POOL_BLOCKS, 64>>>(batch, Wout, bout, out);
}

// round 17
// speedup vs baseline: 2.4902x; 2.4902x over previous
#include <cuda_runtime.h>
#include <cuda_bf16.h>
#include <cuda_fp16.h>

#define N_NODES 100000
#define N_EDGES 3200000
#define IN_DIM 128
#define HID 64
#define N_GRAPHS 64
#define BN_EPS 1e-5f

#define SCAN_NBLK 98   // ceil(100000 / 1024)

// ---------------- scratch ----------------
__device__ __align__(16) float g_dinv[N_NODES];
__device__ __align__(16) int   g_count[N_NODES];
__device__ __align__(16) int   g_off[N_NODES + 1];
__device__ __align__(16) int   g_cursor[N_NODES];
__device__ __align__(16) int   g_blocksum[SCAN_NBLK];
__device__ __align__(16) float2 g_csr[N_EDGES];        // {src_as_float, norm}
__device__ __align__(16) __half g_h[N_NODES * HID];    // gemm1 out (fp16)
__device__ __align__(16) __half g_h2[N_NODES * HID];   // gemm2 out (fp16)
__device__ __align__(16) float g_agg[N_NODES * HID];   // aggregation out (fp32)
__device__ double g_stats[4 * HID];
__device__ float g_A1[HID], g_B1[HID], g_A2[HID], g_B2[HID];
__device__ float g_pool[N_GRAPHS * HID];
__device__ float g_cnt[N_GRAPHS];

// ---------------- init ----------------
__global__ void init_kernel() {
    int t = blockIdx.x * blockDim.x + threadIdx.x;
    if (t < N_NODES) { g_dinv[t] = 1.0f; g_count[t] = 0; }
    if (t < 4 * HID) g_stats[t] = 0.0;
    if (t < N_GRAPHS * HID) g_pool[t] = 0.0f;
    if (t < N_GRAPHS) g_cnt[t] = 0.0f;
    if (t == 0) g_off[N_NODES] = N_EDGES;
}

// ---------------- weighted degree + edge histogram ----------------
__global__ void deg_count_kernel(const int* __restrict__ col,
                                 const float* __restrict__ w) {
    int e = blockIdx.x * blockDim.x + threadIdx.x;
    if (e < N_EDGES) {
        int c = col[e];
        atomicAdd(&g_dinv[c], w[e]);
        atomicAdd(&g_count[c], 1);
    }
}

__global__ void rsqrt_kernel() {
    int i = blockIdx.x * blockDim.x + threadIdx.x;
    if (i < N_NODES) g_dinv[i] = rsqrtf(g_dinv[i]);
}

// ---------------- 2-phase exclusive scan over counts ----------------------
__global__ void scan_phaseA() {
    int blk = blockIdx.x;
    int tid = threadIdx.x;  // 256 threads
    int base = blk * 1024 + tid * 4;
    int s = 0;
#pragma unroll
    for (int i = 0; i < 4; i++) {
        int idx = base + i;
        if (idx < N_NODES) s += g_count[idx];
    }
    __shared__ int sh[256];
    sh[tid] = s;
    __syncthreads();
    for (int off = 128; off > 0; off >>= 1) {
        if (tid < off) sh[tid] += sh[tid + off];
        __syncthreads();
    }
    if (tid == 0) g_blocksum[blk] = sh[0];
}

// Phase C: self-computed block offset (sum of preceding block sums) + local scan
__global__ void scan_phaseC() {
    int blk = blockIdx.x;
    int tid = threadIdx.x;  // 256 threads
    __shared__ int sh[256];
    int v = (tid < blk) ? g_blocksum[tid] : 0;  // blk <= 97 < 256
    sh[tid] = v;
    __syncthreads();
    for (int off = 128; off > 0; off >>= 1) {
        if (tid < off) sh[tid] += sh[tid + off];
        __syncthreads();
    }
    int blockoff = sh[0];
    __syncthreads();
    int base = blk * 1024 + tid * 4;
    int c0 = 0, c1 = 0, c2 = 0, c3 = 0;
    if (base + 0 < N_NODES) c0 = g_count[base + 0];
    if (base + 1 < N_NODES) c1 = g_count[base + 1];
    if (base + 2 < N_NODES) c2 = g_count[base + 2];
    if (base + 3 < N_NODES) c3 = g_count[base + 3];
    int s = c0 + c1 + c2 + c3;
    sh[tid] = s;
    __syncthreads();
    for (int off = 1; off < 256; off <<= 1) {
        int u = (tid >= off) ? sh[tid - off] : 0;
        __syncthreads();
        sh[tid] += u;
        __syncthreads();
    }
    int run = blockoff + sh[tid] - s;
    if (base + 0 < N_NODES) { g_off[base + 0] = run; g_cursor[base + 0] = run; run += c0; }
    if (base + 1 < N_NODES) { g_off[base + 1] = run; g_cursor[base + 1] = run; run += c1; }
    if (base + 2 < N_NODES) { g_off[base + 2] = run; g_cursor[base + 2] = run; run += c2; }
    if (base + 3 < N_NODES) { g_off[base + 3] = run; g_cursor[base + 3] = run; run += c3; }
}

// ---------------- CSR fill (cursor atomics; packed 8B store) --------------
__global__ void fill_kernel(const int* __restrict__ row,
                            const int* __restrict__ col,
                            const float* __restrict__ w) {
    int e = blockIdx.x * blockDim.x + threadIdx.x;
    if (e >= N_EDGES) return;
    int r = row[e];
    int c = col[e];
    int pos = atomicAdd(&g_cursor[c], 1);
    g_csr[pos] = make_float2(__int_as_float(r), g_dinv[r] * w[e] * g_dinv[c]);
}

// ---------------- register-blocked GEMM: h16[n,64] = X[n,K] @ W[K,64] ----
// 256 threads, tile 32x64, 8 outputs/thread (4 rows x 2 cols), fp16 output.
// Warp-uniform rg -> sX reads are broadcast (no bank conflicts).
// WHICH==0: X = Xin, out = g_h.  WHICH==1: X = relu(A1*g_agg+B1), out = g_h2.
template <int K, int WHICH>
__global__ void gemm_kernel(const float* __restrict__ Xin,
                            const float* __restrict__ W) {
    __shared__ float sX[32][K];
    __shared__ float sW[K * 64];
    const float* X = WHICH ? (const float*)g_agg : Xin;
    __half2* out = reinterpret_cast<__half2*>(WHICH ? g_h2 : g_h);
    int tid = threadIdx.x;
    int node0 = blockIdx.x * 32;
    for (int i = tid; i < K * 64; i += 256) sW[i] = W[i];
    for (int i = tid; i < 32 * K; i += 256) {
        int r = i / K, c = i % K;
        float v = X[(size_t)(node0 + r) * K + c];
        if (WHICH) v = fmaxf(fmaf(g_A1[c], v, g_B1[c]), 0.0f);
        sX[r][c] = v;
    }
    __syncthreads();
    int c2 = (tid & 31) * 2;   // column pair
    int rg = tid >> 5;         // warp-uniform -> rows rg, rg+8, rg+16, rg+24
    float a0x = 0, a0y = 0, a1x = 0, a1y = 0, a2x = 0, a2y = 0, a3x = 0, a3y = 0;
#pragma unroll
    for (int k = 0; k < K; k++) {
        float2 wv = *(const float2*)&sW[k * 64 + c2];
        float x0 = sX[rg][k];
        float x1 = sX[rg + 8][k];
        float x2 = sX[rg + 16][k];
        float x3 = sX[rg + 24][k];
        a0x = fmaf(x0, wv.x, a0x); a0y = fmaf(x0, wv.y, a0y);
        a1x = fmaf(x1, wv.x, a1x); a1y = fmaf(x1, wv.y, a1y);
        a2x = fmaf(x2, wv.x, a2x); a2y = fmaf(x2, wv.y, a2y);
        a3x = fmaf(x3, wv.x, a3x); a3y = fmaf(x3, wv.y, a3y);
    }
    int jp = c2 >> 1;
    out[(size_t)(node0 + rg) * 32 + jp]      = __floats2half2_rn(a0x, a0y);
    out[(size_t)(node0 + rg + 8) * 32 + jp]  = __floats2half2_rn(a1x, a1y);
    out[(size_t)(node0 + rg + 16) * 32 + jp] = __floats2half2_rn(a2x, a2y);
    out[(size_t)(node0 + rg + 24) * 32 + jp] = __floats2half2_rn(a3x, a3y);
}

// ---------------- CSR gather-aggregate (warp-per-node, fp16 h, MLP=4) -----
// agg[n,:] = dinv[n]^2*h[n,:] + b + sum_k norm[k]*h[src[k],:]
__global__ void aggregate_kernel(const float* __restrict__ b, int which) {
    const __half2* h = reinterpret_cast<const __half2*>(which ? g_h2 : g_h);
    int node = blockIdx.x * 8 + (threadIdx.x >> 5);
    int j2 = threadIdx.x & 31;   // channel pair index
    float2 bj = ((const float2*)b)[j2];
    float d = g_dinv[node];
    float d2 = d * d;
    float2 hf = __half22float2(h[(size_t)node * 32 + j2]);
    float2 acc;
    acc.x = fmaf(d2, hf.x, bj.x);
    acc.y = fmaf(d2, hf.y, bj.y);
    int s = g_off[node];
    int e = g_off[node + 1];
    int k = s;
    for (; k + 3 < e; k += 4) {
        float2 p0 = g_csr[k];
        float2 p1 = g_csr[k + 1];
        float2 p2 = g_csr[k + 2];
        float2 p3 = g_csr[k + 3];
        __half2 v0 = h[(size_t)__float_as_int(p0.x) * 32 + j2];
        __half2 v1 = h[(size_t)__float_as_int(p1.x) * 32 + j2];
        __half2 v2 = h[(size_t)__float_as_int(p2.x) * 32 + j2];
        __half2 v3 = h[(size_t)__float_as_int(p3.x) * 32 + j2];
        float2 f0 = __half22float2(v0);
        float2 f1 = __half22float2(v1);
        float2 f2 = __half22float2(v2);
        float2 f3 = __half22float2(v3);
        acc.x = fmaf(p0.y, f0.x, acc.x); acc.y = fmaf(p0.y, f0.y, acc.y);
        acc.x = fmaf(p1.y, f1.x, acc.x); acc.y = fmaf(p1.y, f1.y, acc.y);
        acc.x = fmaf(p2.y, f2.x, acc.x); acc.y = fmaf(p2.y, f2.y, acc.y);
        acc.x = fmaf(p3.y, f3.x, acc.x); acc.y = fmaf(p3.y, f3.y, acc.y);
    }
    for (; k < e; k++) {
        float2 p = g_csr[k];
        float2 f = __half22float2(h[(size_t)__float_as_int(p.x) * 32 + j2]);
        acc.x = fmaf(p.y, f.x, acc.x);
        acc.y = fmaf(p.y, f.y, acc.y);
    }
    ((float2*)g_agg)[(size_t)node * 32 + j2] = acc;
}

// ---------------- BN stats ----------------
__global__ void stats_kernel(int off) {
    int j = threadIdx.x & 63;
    int g = threadIdx.x >> 6;
    int r0 = blockIdx.x * 512;
    int rend = min(r0 + 512, N_NODES);
    float s = 0.0f, s2 = 0.0f;
    for (int r = r0 + g; r < rend; r += 4) {
        float v = g_agg[(size_t)r * 64 + j];
        s += v;
        s2 = fmaf(v, v, s2);
    }
    __shared__ float sh[256], sh2[256];
    sh[threadIdx.x] = s;
    sh2[threadIdx.x] = s2;
    __syncthreads();
    if (g == 0) {
        s = sh[j] + sh[64 + j] + sh[128 + j] + sh[192 + j];
        s2 = sh2[j] + sh2[64 + j] + sh2[128 + j] + sh2[192 + j];
        atomicAdd(&g_stats[off + j], (double)s);
        atomicAdd(&g_stats[off + 64 + j], (double)s2);
    }
}

__global__ void finalize_kernel(const float* __restrict__ gamma,
                                const float* __restrict__ beta,
                                int off, int layer) {
    int j = threadIdx.x;
    double mean = g_stats[off + j] / (double)N_NODES;
    double var = g_stats[off + 64 + j] / (double)N_NODES - mean * mean;
    float istd = rsqrtf((float)var + BN_EPS);
    float a = gamma[j] * istd;
    float bb = beta[j] - a * (float)mean;
    if (layer == 0) { g_A1[j] = a; g_B1[j] = bb; }
    else            { g_A2[j] = a; g_B2[j] = bb; }
}

// ---------------- fused BN2+ReLU + segment-sum pool (batch sorted) --------
__global__ void pool_kernel(const int* __restrict__ batch) {
    int j = threadIdx.x;
    int r0 = blockIdx.x * 128;
    int rend = min(r0 + 128, N_NODES);
    if (r0 >= N_NODES) return;
    float A = g_A2[j], B = g_B2[j];
    int cur = batch[r0];
    float s = 0.0f;
    int c = 0;
    for (int r = r0; r < rend; r++) {
        int gg = batch[r];
        if (gg != cur) {
            atomicAdd(&g_pool[cur * 64 + j], s);
            if (j == 0) atomicAdd(&g_cnt[cur], (float)c);
            s = 0.0f; c = 0; cur = gg;
        }
        float v = fmaxf(fmaf(A, g_agg[(size_t)r * 64 + j], B), 0.0f);
        s += v;
        c++;
    }
    atomicAdd(&g_pool[cur * 64 + j], s);
    if (j == 0) atomicAdd(&g_cnt[cur], (float)c);
}

// ---------------- output head ----------------
__global__ void out_kernel(const float* __restrict__ Wout,
                           const float* __restrict__ bout,
                           float* __restrict__ out) {
    int g = threadIdx.x;
    float c = fmaxf(g_cnt[g], 1.0f);
    float s = 0.0f;
#pragma unroll
    for (int j = 0; j < HID; j++) s = fmaf(g_pool[g * HID + j], Wout[j], s);
    out[g] = s / c + bout[0];
}

// ---------------- launch ----------------
extern "C" void kernel_launch(void* const* d_in, const int* in_sizes, int n_in,
                              void* d_out, int out_size) {
    const float* x = (const float*)d_in[0];
    const int* ei = (const int*)d_in[1];
    const float* ew = (const float*)d_in[2];
    const int* batch = (const int*)d_in[3];
    const float* W1 = (const float*)d_in[4];
    const float* b1 = (const float*)d_in[5];
    const float* W2 = (const float*)d_in[6];
    const float* b2 = (const float*)d_in[7];
    const float* g1 = (const float*)d_in[8];
    const float* be1 = (const float*)d_in[9];
    const float* g2 = (const float*)d_in[10];
    const float* be2 = (const float*)d_in[11];
    const float* Wout = (const float*)d_in[12];
    const float* bout = (const float*)d_in[13];
    float* out = (float*)d_out;

    const int* row = ei;
    const int* col = ei + N_EDGES;

    const int EB = (N_EDGES + 255) / 256;
    const int NB = (N_NODES + 255) / 256;
    const int SB = (N_NODES + 511) / 512;
    const int PB = (N_NODES + 127) / 128;
    const int GB = N_NODES / 32;   // 3125, exact
    const int AB = N_NODES / 8;    // 12500, exact (warp-per-node)

    // ---- CSR build (once, reused by both layers) ----
    init_kernel<<<NB, 256>>>();
    deg_count_kernel<<<EB, 256>>>(col, ew);
    rsqrt_kernel<<<NB, 256>>>();
    scan_phaseA<<<SCAN_NBLK, 256>>>();
    scan_phaseC<<<SCAN_NBLK, 256>>>();   // self-computed offsets (no phaseB)
    fill_kernel<<<EB, 256>>>(row, col, ew);

    // ---- layer 1 ----
    gemm_kernel<IN_DIM, 0><<<GB, 256>>>(x, W1);
    aggregate_kernel<<<AB, 256>>>(b1, 0);
    stats_kernel<<<SB, 256>>>(0);
    finalize_kernel<<<1, 64>>>(g1, be1, 0, 0);

    // ---- layer 2 (BN1+ReLU fused into GEMM X-load) ----
    gemm_kernel<HID, 1><<<GB, 256>>>(x /*unused*/, W2);
    aggregate_kernel<<<AB, 256>>>(b2, 1);
    stats_kernel<<<SB, 256>>>(128);
    finalize_kernel<<<1, 64>>>(g2, be2, 128, 1);

    // ---- pool + head ----
    pool_kernel<<<PB, 64>>>(batch);
    out_kernel<<<1, 64>>>(Wout, bout, out);
}